// round 1
// baseline (speedup 1.0000x reference)
#include <cuda_runtime.h>

// Problem constants (fixed by the dataset)
#define NN  100000     // nodes
#define EE  1600000    // edges
#define HH  4          // heads
#define DD  32         // dim per head
#define HD  128        // H*D
#define EFD 32         // edge feat dim
#define ETN 8          // edge types
#define NEG_SLOPE 0.2f

// Scratch (device globals — no allocation allowed)
__device__ float g_fs[(size_t)NN * HD];   // feat * fc[type]
__device__ float g_el[(size_t)NN * HH];
__device__ float g_er[(size_t)NN * HH];
__device__ float g_s [(size_t)NN * HH];   // softmax denominators
__device__ float g_ee[ETN * HH];

// ---------------------------------------------------------------------------
// Kernel 1: per-node. fs = feat*fc[type]; el = sum_d fs*attn_l; er likewise.
// Also zeroes g_s (consumed later by edge pass A).
// block = 128 threads = one node; warp h handles head h (lane = d).
// ---------------------------------------------------------------------------
__global__ void node_kernel(const float* __restrict__ feat,
                            const float* __restrict__ fc,
                            const float* __restrict__ attn_l,
                            const float* __restrict__ attn_r,
                            const int*   __restrict__ ntype) {
    int node = blockIdx.x;
    int tid  = threadIdx.x;          // 0..127
    int h    = tid >> 5;
    int lane = tid & 31;

    int ty = ntype[node];
    float f = feat[(size_t)node * HD + tid];
    float v = f * fc[ty * HD + tid];
    g_fs[(size_t)node * HD + tid] = v;

    float pl = v * attn_l[tid];
    float pr = v * attn_r[tid];
    #pragma unroll
    for (int o = 16; o > 0; o >>= 1) {
        pl += __shfl_down_sync(0xffffffffu, pl, o);
        pr += __shfl_down_sync(0xffffffffu, pr, o);
    }
    if (lane == 0) {
        g_el[node * HH + h] = pl;
        g_er[node * HH + h] = pr;
        g_s [node * HH + h] = 0.0f;
    }
}

// ---------------------------------------------------------------------------
// Kernel 2: ee[t,h] = sum_f (edge_emb[t] . W_e[h*EF+f]) * attn_e[h,f]
// Tiny: 32 outputs, one block of 32 threads.
// ---------------------------------------------------------------------------
__global__ void ee_kernel(const float* __restrict__ edge_emb,
                          const float* __restrict__ W_e,
                          const float* __restrict__ attn_e) {
    int t  = threadIdx.x;            // 0..31
    int et = t >> 2;
    int h  = t & 3;
    const float* em = edge_emb + et * EFD;
    float acc = 0.0f;
    for (int f = 0; f < EFD; f++) {
        const float* w = W_e + (h * EFD + f) * EFD;
        float dot = 0.0f;
        #pragma unroll 8
        for (int k = 0; k < EFD; k++) dot += em[k] * w[k];
        acc += dot * attn_e[h * EFD + f];
    }
    g_ee[et * HH + h] = acc;
}

// ---------------------------------------------------------------------------
// Kernel 3 (edge pass A): per-edge score -> exp -> store into a-output region,
// atomicAdd into per-(dst,h) denominator. Softmax max-shift is omitted: it
// cancels in the normalization and scores here are O(1), so exp() is safe.
// ---------------------------------------------------------------------------
__global__ void edge_score_kernel(const int* __restrict__ src,
                                  const int* __restrict__ dst,
                                  const int* __restrict__ efeat,
                                  float* __restrict__ a_out) {
    int e = blockIdx.x * blockDim.x + threadIdx.x;
    if (e >= EE) return;
    int s_ = src[e];
    int d_ = dst[e];
    int t_ = efeat[e];

    float4 el4 = *(const float4*)(g_el + (size_t)s_ * HH);
    float4 er4 = *(const float4*)(g_er + (size_t)d_ * HH);
    float4 ee4 = *(const float4*)(g_ee + t_ * HH);

    float x0 = el4.x + er4.x + ee4.x;
    float x1 = el4.y + er4.y + ee4.y;
    float x2 = el4.z + er4.z + ee4.z;
    float x3 = el4.w + er4.w + ee4.w;
    x0 = (x0 > 0.0f) ? x0 : NEG_SLOPE * x0;
    x1 = (x1 > 0.0f) ? x1 : NEG_SLOPE * x1;
    x2 = (x2 > 0.0f) ? x2 : NEG_SLOPE * x2;
    x3 = (x3 > 0.0f) ? x3 : NEG_SLOPE * x3;

    float4 ex;
    ex.x = __expf(x0);
    ex.y = __expf(x1);
    ex.z = __expf(x2);
    ex.w = __expf(x3);

    *(float4*)(a_out + (size_t)e * HH) = ex;

    float* sp = g_s + (size_t)d_ * HH;
    atomicAdd(sp + 0, ex.x);
    atomicAdd(sp + 1, ex.y);
    atomicAdd(sp + 2, ex.z);
    atomicAdd(sp + 3, ex.w);
}

// ---------------------------------------------------------------------------
// Kernel 4 (edge pass B): warp per edge.
//   a = ex / s[dst]  (written to a-output region, overwriting ex)
//   rst[dst,h,d] += fs[src,h,d] * a[h]    (128 atomics / edge)
// rst was pre-initialized to feat (the residual), so no final add pass.
// ---------------------------------------------------------------------------
__global__ void edge_agg_kernel(const int* __restrict__ src,
                                const int* __restrict__ dst,
                                float* __restrict__ a_out,
                                float* __restrict__ rst) {
    int gwid = (blockIdx.x * blockDim.x + threadIdx.x) >> 5;
    int lane = threadIdx.x & 31;
    if (gwid >= EE) return;
    int e  = gwid;
    int s_ = src[e];
    int d_ = dst[e];

    float4 ex = *(const float4*)(a_out + (size_t)e * HH);
    float4 sv = *(const float4*)(g_s   + (size_t)d_ * HH);
    float4 a;
    a.x = ex.x / sv.x;
    a.y = ex.y / sv.y;
    a.z = ex.z / sv.z;
    a.w = ex.w / sv.w;

    if (lane == 0) *(float4*)(a_out + (size_t)e * HH) = a;

    const float* fsp = g_fs + (size_t)s_ * HD;
    float*       rp  = rst  + (size_t)d_ * HD;

    atomicAdd(rp +  0 + lane, fsp[ 0 + lane] * a.x);
    atomicAdd(rp + 32 + lane, fsp[32 + lane] * a.y);
    atomicAdd(rp + 64 + lane, fsp[64 + lane] * a.z);
    atomicAdd(rp + 96 + lane, fsp[96 + lane] * a.w);
}

// ---------------------------------------------------------------------------
extern "C" void kernel_launch(void* const* d_in, const int* in_sizes, int n_in,
                              void* d_out, int out_size) {
    const float* feat     = (const float*)d_in[0];
    const float* fc       = (const float*)d_in[1];
    const float* edge_emb = (const float*)d_in[2];
    const float* W_e      = (const float*)d_in[3];
    const float* attn_l   = (const float*)d_in[4];
    const float* attn_r   = (const float*)d_in[5];
    const float* attn_e   = (const float*)d_in[6];
    const int*   ntype    = (const int*)d_in[7];
    const int*   efeat    = (const int*)d_in[8];
    const int*   src      = (const int*)d_in[9];
    const int*   dst      = (const int*)d_in[10];

    float* rst   = (float*)d_out;                       // [N, H, D]
    float* a_out = (float*)d_out + (size_t)NN * HD;     // [E, H, 1]

    // Residual: rst starts as h (original features)
    cudaMemcpyAsync(rst, feat, (size_t)NN * HD * sizeof(float),
                    cudaMemcpyDeviceToDevice);

    node_kernel<<<NN, 128>>>(feat, fc, attn_l, attn_r, ntype);
    ee_kernel<<<1, 32>>>(edge_emb, W_e, attn_e);

    {
        int threads = 256;
        int blocks = (EE + threads - 1) / threads;
        edge_score_kernel<<<blocks, threads>>>(src, dst, efeat, a_out);
    }
    {
        int threads = 256;                    // 8 warps = 8 edges per block
        int blocks = (EE + 8 - 1) / 8;
        edge_agg_kernel<<<blocks, threads>>>(src, dst, a_out, rst);
    }
}